// round 11
// baseline (speedup 1.0000x reference)
#include <cuda_runtime.h>
#include <cuda_fp16.h>
#include <cstdint>

#define NN 100000
#define NE 800000
#define FIN 256
#define HID 128
#define NCLS 32
#define NPRE 128
#define NWORK 296   // persistent GEMM workers: 2 per SM x 148

// ---------------- scratch ----------------
__device__ int   g_cnt[NN];
__device__ int   g_rowptr[NN];
__device__ int   g_cursor[NN];
__device__ int   g_part[NPRE];
__device__ float g_dinv[NN];
__device__ int   g_csr[NE];
__device__ int   g_is64;
__device__ int   g_ready = 0;
__device__ int   g_ready2 = 0;
__device__ int   g_tilec = 0;   // dynamic tile counter (reset by last worker each launch)
__device__ int   g_done = 0;
__device__ unsigned g_bar_cnt = 0;
__device__ volatile unsigned g_bar_gen = 0;
__device__ __align__(16) __half g_y1h[(size_t)NN * HID];   // dinv * (X@W1), fp16
__device__ __align__(16) __half g_y2h[(size_t)NN * NCLS];  // dinv * (h@W2), fp16
__device__ __align__(16) __half g_W1h[HID * FIN];          // W1^T fp16 [n][k]

// ---------------- helpers ----------------
__device__ __forceinline__ int load_idx(const void* p, long long i, int is64) {
    if (is64) return (int)((const long long*)p)[i];
    return ((const int*)p)[i];
}
__device__ __forceinline__ uint32_t smem_u32(const void* p) {
    uint32_t a;
    asm("{ .reg .u64 t; cvta.to.shared.u64 t, %1; cvt.u32.u64 %0, t; }" : "=r"(a) : "l"(p));
    return a;
}
__device__ __forceinline__ void ldsm4(uint4& r, uint32_t addr) {
    asm volatile("ldmatrix.sync.aligned.m8n8.x4.shared.b16 {%0,%1,%2,%3}, [%4];"
                 : "=r"(r.x), "=r"(r.y), "=r"(r.z), "=r"(r.w) : "r"(addr));
}
__device__ __forceinline__ void mma16816(float c[4], const uint4& a, uint32_t b0, uint32_t b1) {
    asm volatile(
        "mma.sync.aligned.m16n8k16.row.col.f32.f16.f16.f32 "
        "{%0,%1,%2,%3}, {%4,%5,%6,%7}, {%8,%9}, {%0,%1,%2,%3};"
        : "+f"(c[0]), "+f"(c[1]), "+f"(c[2]), "+f"(c[3])
        : "r"(a.x), "r"(a.y), "r"(a.z), "r"(a.w), "r"(b0), "r"(b1));
}
__device__ __forceinline__ uint32_t packh2(float a, float b) {
    __half2 h = __floats2half2_rn(a, b);
    return *(uint32_t*)&h;
}
__device__ __forceinline__ void cpasync16(uint32_t dst, const void* src) {
    asm volatile("cp.async.cg.shared.global [%0], [%1], 16;" :: "r"(dst), "l"(src));
}
#define CP_COMMIT() asm volatile("cp.async.commit_group;" ::: "memory")
#define CP_WAIT0()  asm volatile("cp.async.wait_group 0;" ::: "memory")

__device__ __forceinline__ void pre_grid_bar() {
    __syncthreads();
    if (threadIdx.x == 0) {
        __threadfence();
        unsigned g = g_bar_gen;
        if (atomicAdd(&g_bar_cnt, 1u) == NPRE - 1) {
            g_bar_cnt = 0;
            __threadfence();
            g_bar_gen = g + 1;
        } else {
            while (g_bar_gen == g) { __nanosleep(64); }
        }
    }
    __syncthreads();
}

__device__ __forceinline__ int block_exscan(int v, int* p_total, int* wsum) {
    const int lane = threadIdx.x & 31, w = threadIdx.x >> 5;
    const int nw = blockDim.x >> 5;
    int x = v;
#pragma unroll
    for (int o = 1; o < 32; o <<= 1) {
        int y = __shfl_up_sync(0xffffffffu, x, o);
        if (lane >= o) x += y;
    }
    if (lane == 31) wsum[w] = x;
    __syncthreads();
    if (w == 0) {
        int s = (lane < nw) ? wsum[lane] : 0;
#pragma unroll
        for (int o = 1; o < 32; o <<= 1) {
            int y = __shfl_up_sync(0xffffffffu, s, o);
            if (lane >= o) s += y;
        }
        wsum[lane] = s;
    }
    __syncthreads();
    int base = (w > 0) ? wsum[w - 1] : 0;
    *p_total = wsum[31];
    __syncthreads();
    return base + (x - v);
}

// ================= FAT: preproc (blocks < NPRE) + persistent fp16-MMA GEMM1 =================
// GEMM dyn smem (112 KB): [0,32K) A32 staging; [32K,48K) A16; [48K,112K) Bfull (4 kt-segments)
__global__ __launch_bounds__(512, 2) void k_fat(const float* __restrict__ X,
                                                const float* __restrict__ W1,
                                                const void* __restrict__ ei,
                                                int n, int e) {
    extern __shared__ char dsm[];
    __shared__ int p_wsum[32];
    __shared__ int p_boff;
    const int tid = threadIdx.x;

    if (blockIdx.x < NPRE) {
        const int gt = blockIdx.x * 512 + tid;
        const int GT = NPRE * 512;
        for (int i = gt; i < n; i += GT) g_cnt[i] = 0;
        for (int i = gt; i < HID * FIN; i += GT) {
            int nn2 = i >> 8, k = i & 255;
            g_W1h[i] = __float2half(W1[(size_t)k * HID + nn2]);
        }
        if (gt == 0) {
            const long long* p = (const long long*)ei;
            int ok = 1;
            for (int j = 0; j < 256; j++) {
                long long v = p[j];
                if (v < 0 || v >= n) { ok = 0; break; }
            }
            g_is64 = ok;
        }
        pre_grid_bar();
        if (blockIdx.x == 0 && tid == 0) *(volatile int*)&g_ready = 1;
        const int is64 = g_is64;
        for (int i = gt; i < e; i += GT) {
            int d = load_idx(ei, (long long)e + i, is64);
            atomicAdd(&g_cnt[d], 1);
        }
        pre_grid_bar();
        const int L = (n + GT - 1) / GT;
        const int base = gt * L;
        const int end = (base + L < n) ? base + L : n;
        int s = 0;
        for (int i = base; i < end; i++) s += __ldcg(&g_cnt[i]);
        int tot;
        int ex = block_exscan(s, &tot, p_wsum);
        if (tid == 0) g_part[blockIdx.x] = tot;
        pre_grid_bar();
        {
            int v = (tid < NPRE) ? __ldcg(&g_part[tid]) : 0;
            int t2;
            int ex2 = block_exscan(v, &t2, p_wsum);
            if (tid == (int)blockIdx.x) p_boff = ex2;
            __syncthreads();
            int run = p_boff + ex;
            for (int i = base; i < end; i++) {
                int c = __ldcg(&g_cnt[i]);
                g_rowptr[i] = run;
                g_cursor[i] = run;
                g_dinv[i] = rsqrtf((float)(c + 1));
                run += c;
            }
        }
        pre_grid_bar();
        if (blockIdx.x == 0 && tid == 0) *(volatile int*)&g_ready2 = 1;
        for (int i = gt; i < e; i += GT) {
            int s0 = load_idx(ei, i, is64);
            int d0 = load_idx(ei, (long long)e + i, is64);
            int pos = atomicAdd(&g_cursor[d0], 1);
            g_csr[pos] = s0;
        }
        return;
    }

    // -------- persistent GEMM1 workers --------
    while (*(volatile int*)&g_ready == 0) { __nanosleep(128); }
    __threadfence();

    const int lane = tid & 31, warp = tid >> 5;
    const int wm = warp & 3, wn = warp >> 2;
    const uint32_t sbase = smem_u32(dsm);
    const uint32_t sA32 = sbase;
    const uint32_t sA16 = sbase + 32768;
    const uint32_t sBf  = sbase + 49152;

    const int lrow = tid >> 2;
    const int lq = tid & 3;
    const int rsw = lrow & 7;

    // load full B = W1^T fp16 (64 KB) once, swizzled per kt-segment
    {
        const char* bgp = (const char*)(g_W1h + (size_t)lrow * FIN);
#pragma unroll
        for (int kt = 0; kt < 4; kt++)
#pragma unroll
            for (int j = 0; j < 2; j++) {
                int cc = lq * 2 + j;
                cpasync16(sBf + kt * 16384 + lrow * 128 + ((cc ^ rsw) * 16),
                          bgp + kt * 128 + cc * 16);
            }
        CP_COMMIT();
    }

    const int T = (n + 127) / 128;
    const char* agp = (const char*)X;

#define SET_A(tt) do {                                                       \
        int _ar = (tt) * 128 + lrow; if (_ar >= n) _ar = n - 1;              \
        agp = (const char*)(X + (size_t)_ar * FIN);                          \
    } while (0)
#define ISSUE_A32(kt) do {                                                   \
        _Pragma("unroll")                                                    \
        for (int j = 0; j < 4; j++)                                          \
            cpasync16(sA32 + lrow * 256 + lq * 64 + j * 16,                  \
                      agp + (kt) * 256 + lq * 64 + j * 16);                  \
        CP_COMMIT();                                                         \
    } while (0)
#define CONVERT_A() do {                                                     \
        _Pragma("unroll")                                                    \
        for (int j = 0; j < 2; j++) {                                        \
            int cc = lq * 2 + j;                                             \
            float4 v0, v1;                                                   \
            asm volatile("ld.shared.v4.f32 {%0,%1,%2,%3}, [%4];"             \
                : "=f"(v0.x), "=f"(v0.y), "=f"(v0.z), "=f"(v0.w)             \
                : "r"(sA32 + lrow * 256 + cc * 32));                         \
            asm volatile("ld.shared.v4.f32 {%0,%1,%2,%3}, [%4];"             \
                : "=f"(v1.x), "=f"(v1.y), "=f"(v1.z), "=f"(v1.w)             \
                : "r"(sA32 + lrow * 256 + cc * 32 + 16));                    \
            uint4 u = make_uint4(packh2(v0.x, v0.y), packh2(v0.z, v0.w),     \
                                 packh2(v1.x, v1.y), packh2(v1.z, v1.w));    \
            asm volatile("st.shared.v4.b32 [%0], {%1,%2,%3,%4};"             \
                :: "r"(sA16 + lrow * 128 + ((cc ^ rsw) * 16)),               \
                   "r"(u.x), "r"(u.y), "r"(u.z), "r"(u.w));                  \
        }                                                                    \
    } while (0)

    __shared__ int s_tile;
    if (tid == 0) s_tile = atomicAdd(&g_tilec, 1);
    __syncthreads();
    int t = s_tile;
    if (t < T) { SET_A(t); ISSUE_A32(0); }

    const int lr = lane & 15, lhi = lane >> 4, lsw = lane & 7;
    while (t < T) {
        float c[2][4][4];
#pragma unroll
        for (int i = 0; i < 2; i++)
#pragma unroll
            for (int j = 0; j < 4; j++)
#pragma unroll
                for (int v = 0; v < 4; v++) c[i][j][v] = 0.f;

        int tn = T;
        for (int kt = 0; kt < 4; kt++) {
            CP_WAIT0();
            __syncthreads();   // prev compute done reading A16
            CONVERT_A();
            if (kt < 3) {
                ISSUE_A32(kt + 1);
            } else {
                if (tid == 0) s_tile = atomicAdd(&g_tilec, 1);
            }
            __syncthreads();   // publish A16 (and s_tile on kt=3)
            if (kt == 3) {
                tn = s_tile;
                if (tn < T) { SET_A(tn); ISSUE_A32(0); }
            }
#pragma unroll
            for (int kp = 0; kp < 4; kp++) {
                const int ch = ((kp * 2 + lhi) ^ lsw) * 16;
                uint4 af[2];
#pragma unroll
                for (int mt = 0; mt < 2; mt++)
                    ldsm4(af[mt], sA16 + (wm * 32 + mt * 16 + lr) * 128 + ch);
                uint4 bf[2];
#pragma unroll
                for (int bt = 0; bt < 2; bt++)
                    ldsm4(bf[bt], sBf + kt * 16384 + (wn * 32 + bt * 16 + lr) * 128 + ch);
#pragma unroll
                for (int mt = 0; mt < 2; mt++)
#pragma unroll
                    for (int bt = 0; bt < 2; bt++) {
                        mma16816(c[mt][2 * bt],     af[mt], bf[bt].x, bf[bt].z);
                        mma16816(c[mt][2 * bt + 1], af[mt], bf[bt].y, bf[bt].w);
                    }
            }
        }

        // epilogue: y1 = dinv[r] * xw1[r], fp16
        while (*(volatile int*)&g_ready2 == 0) { __nanosleep(128); }
        const int row0 = t * 128;
        const int g = lane >> 2, cp = (lane & 3) * 2;
#pragma unroll
        for (int mt = 0; mt < 2; mt++) {
            int r1 = row0 + wm * 32 + mt * 16 + g;
            int r2 = r1 + 8;
            float d1 = (r1 < n) ? g_dinv[r1] : 0.f;
            float d2 = (r2 < n) ? g_dinv[r2] : 0.f;
#pragma unroll
            for (int nt = 0; nt < 4; nt++) {
                int col = wn * 32 + nt * 8 + cp;
                if (r1 < n)
                    *(__half2*)&g_y1h[(size_t)r1 * HID + col] =
                        __floats2half2_rn(d1 * c[mt][nt][0], d1 * c[mt][nt][1]);
                if (r2 < n)
                    *(__half2*)&g_y1h[(size_t)r2 * HID + col] =
                        __floats2half2_rn(d2 * c[mt][nt][2], d2 * c[mt][nt][3]);
            }
        }
        t = tn;
    }

    CP_WAIT0();
    __syncthreads();
    if (tid == 0) {
        int old = atomicAdd(&g_done, 1);
        if (old == NWORK - 1) {       // last worker resets counters for next graph replay
            atomicExch(&g_tilec, 0);
            atomicExch(&g_done, 0);
            __threadfence();
        }
    }
}

// ========== Agg1 + GEMM2 fused: y2 = dinv * (relu(dinv*(sum y1) + b1) @ W2), fp16 out ==========
__global__ __launch_bounds__(256) void k_aggmm(const float* __restrict__ b1,
                                               const float* __restrict__ W2, int n) {
    __shared__ __align__(16) __half hs[64 * 128];  // 16 KB
    __shared__ __align__(16) __half Bs[32 * 128];  // 8 KB
    const int tid = threadIdx.x, lane = tid & 31, warp = tid >> 5;
    const int row0 = blockIdx.x * 64;
    const uint32_t sH = smem_u32(hs), sB = smem_u32(Bs);

    {
        const int nn2 = tid >> 3;
        const int kc = (tid & 7) * 16;
        __half tmp[16];
#pragma unroll
        for (int k = 0; k < 16; k++) tmp[k] = __float2half(W2[(size_t)(kc + k) * NCLS + nn2]);
#pragma unroll
        for (int j = 0; j < 2; j++) {
            int cc = kc / 8 + j;
            *(uint4*)((char*)Bs + nn2 * 256 + ((cc ^ (nn2 & 7)) * 16)) = *(uint4*)&tmp[j * 8];
        }
    }

    float4 bb = ((const float4*)b1)[lane];
    const int hc = lane >> 1, hh = (lane & 1) * 8;
#pragma unroll 1
    for (int i = 0; i < 8; i++) {
        int node = row0 + warp * 8 + i;
        if (node >= n) break;
        int start = g_rowptr[node];
        int cnt = g_cnt[node];
        float di = g_dinv[node];
        uint2 sv = ((const uint2*)&g_y1h[(size_t)node * HID])[lane];
        float2 s0 = __half22float2(*(__half2*)&sv.x);
        float2 s1 = __half22float2(*(__half2*)&sv.y);
        float4 acc = make_float4(s0.x, s0.y, s1.x, s1.y);
        int t = 0;
        for (; t + 4 <= cnt; t += 4) {
            int e0 = g_csr[start + t],     e1 = g_csr[start + t + 1];
            int e2 = g_csr[start + t + 2], e3 = g_csr[start + t + 3];
            uint2 w0 = ((const uint2*)&g_y1h[(size_t)e0 * HID])[lane];
            uint2 w1 = ((const uint2*)&g_y1h[(size_t)e1 * HID])[lane];
            uint2 w2 = ((const uint2*)&g_y1h[(size_t)e2 * HID])[lane];
            uint2 w3 = ((const uint2*)&g_y1h[(size_t)e3 * HID])[lane];
            float2 a0 = __half22float2(*(__half2*)&w0.x), c0 = __half22float2(*(__half2*)&w0.y);
            float2 a1 = __half22float2(*(__half2*)&w1.x), c1 = __half22float2(*(__half2*)&w1.y);
            float2 a2 = __half22float2(*(__half2*)&w2.x), c2 = __half22float2(*(__half2*)&w2.y);
            float2 a3 = __half22float2(*(__half2*)&w3.x), c3 = __half22float2(*(__half2*)&w3.y);
            acc.x += (a0.x + a1.x) + (a2.x + a3.x);
            acc.y += (a0.y + a1.y) + (a2.y + a3.y);
            acc.z += (c0.x + c1.x) + (c2.x + c3.x);
            acc.w += (c0.y + c1.y) + (c2.y + c3.y);
        }
        for (; t < cnt; t++) {
            int e0 = g_csr[start + t];
            uint2 w0 = ((const uint2*)&g_y1h[(size_t)e0 * HID])[lane];
            float2 a0 = __half22float2(*(__half2*)&w0.x), c0 = __half22float2(*(__half2*)&w0.y);
            acc.x += a0.x; acc.y += a0.y; acc.z += c0.x; acc.w += c0.y;
        }
        float hx = fmaxf(fmaf(di, acc.x, bb.x), 0.f);
        float hy = fmaxf(fmaf(di, acc.y, bb.y), 0.f);
        float hz = fmaxf(fmaf(di, acc.z, bb.z), 0.f);
        float hw = fmaxf(fmaf(di, acc.w, bb.w), 0.f);
        int rl = warp * 8 + i;
        *(uint2*)((char*)hs + rl * 256 + ((hc ^ (rl & 7)) * 16) + hh) =
            make_uint2(packh2(hx, hy), packh2(hz, hw));
    }
    __syncthreads();

    const int wm = warp & 3, wn = warp >> 2;
    float c0[4] = {0.f, 0.f, 0.f, 0.f}, c1[4] = {0.f, 0.f, 0.f, 0.f};
    const int lr = lane & 15, lhi = lane >> 4, lsw = lane & 7;
#pragma unroll
    for (int kp = 0; kp < 8; kp++) {
        const int ch = ((kp * 2 + lhi) ^ lsw) * 16;
        uint4 af, bf;
        ldsm4(af, sH + (wm * 16 + lr) * 256 + ch);
        ldsm4(bf, sB + (wn * 16 + lr) * 256 + ch);
        mma16816(c0, af, bf.x, bf.z);
        mma16816(c1, af, bf.y, bf.w);
    }
    const int g = lane >> 2, cp = (lane & 3) * 2;
    int r1 = row0 + wm * 16 + g;
    int r2 = r1 + 8;
    float d1 = (r1 < n) ? g_dinv[r1] : 0.f;
    float d2 = (r2 < n) ? g_dinv[r2] : 0.f;
    int col = wn * 16 + cp;
    if (r1 < n) {
        *(__half2*)&g_y2h[(size_t)r1 * NCLS + col]     = __floats2half2_rn(d1 * c0[0], d1 * c0[1]);
        *(__half2*)&g_y2h[(size_t)r1 * NCLS + col + 8] = __floats2half2_rn(d1 * c1[0], d1 * c1[1]);
    }
    if (r2 < n) {
        *(__half2*)&g_y2h[(size_t)r2 * NCLS + col]     = __floats2half2_rn(d2 * c0[2], d2 * c0[3]);
        *(__half2*)&g_y2h[(size_t)r2 * NCLS + col + 8] = __floats2half2_rn(d2 * c1[2], d2 * c1[3]);
    }
}

// ---------------- Agg2 + log_softmax: fp16 gathers ----------------
__global__ __launch_bounds__(256) void k_agg2(const float* __restrict__ b2,
                                              float* __restrict__ out, int n) {
    const int tid = threadIdx.x, lane = tid & 31;
    const int grp = lane >> 3, li = lane & 7;
    int node = blockIdx.x * 8 + (tid >> 5);
    if (node >= n) return;
    int start = g_rowptr[node];
    int cnt = g_cnt[node];
    float di = g_dinv[node];
    float4 acc = make_float4(0.f, 0.f, 0.f, 0.f);
    if (grp == 0) {
        uint2 w = ((const uint2*)&g_y2h[(size_t)node * NCLS])[li];
        float2 lo = __half22float2(*(__half2*)&w.x);
        float2 hi = __half22float2(*(__half2*)&w.y);
        acc = make_float4(lo.x, lo.y, hi.x, hi.y);
    }
    for (int t = grp; t < cnt; t += 4) {
        int s = g_csr[start + t];
        uint2 w = ((const uint2*)&g_y2h[(size_t)s * NCLS])[li];
        float2 lo = __half22float2(*(__half2*)&w.x);
        float2 hi = __half22float2(*(__half2*)&w.y);
        acc.x += lo.x; acc.y += lo.y; acc.z += hi.x; acc.w += hi.y;
    }
#pragma unroll
    for (int o = 8; o <= 16; o <<= 1) {
        acc.x += __shfl_xor_sync(0xffffffffu, acc.x, o);
        acc.y += __shfl_xor_sync(0xffffffffu, acc.y, o);
        acc.z += __shfl_xor_sync(0xffffffffu, acc.z, o);
        acc.w += __shfl_xor_sync(0xffffffffu, acc.w, o);
    }
    float4 bb = ((const float4*)b2)[li];
    float4 vv = make_float4(fmaf(di, acc.x, bb.x), fmaf(di, acc.y, bb.y),
                            fmaf(di, acc.z, bb.z), fmaf(di, acc.w, bb.w));
    float m = fmaxf(fmaxf(vv.x, vv.y), fmaxf(vv.z, vv.w));
#pragma unroll
    for (int o = 1; o <= 4; o <<= 1) m = fmaxf(m, __shfl_xor_sync(0xffffffffu, m, o));
    float s4 = __expf(vv.x - m) + __expf(vv.y - m) + __expf(vv.z - m) + __expf(vv.w - m);
#pragma unroll
    for (int o = 1; o <= 4; o <<= 1) s4 += __shfl_xor_sync(0xffffffffu, s4, o);
    float ls = m + logf(s4);
    if (lane < 8)
        ((float4*)&out[(size_t)node * NCLS])[li] =
            make_float4(vv.x - ls, vv.y - ls, vv.z - ls, vv.w - ls);
}

// ---------------- launch ----------------
extern "C" void kernel_launch(void* const* d_in, const int* in_sizes, int n_in,
                              void* d_out, int out_size) {
    const float* X = (const float*)d_in[0];
    const void* EI = d_in[1];
    const float* W1 = (const float*)d_in[2];
    const float* b1 = (const float*)d_in[3];
    const float* W2 = (const float*)d_in[4];
    const float* b2 = (const float*)d_in[5];
    float* out = (float*)d_out;

    int n = in_sizes[0] / FIN;   // 100000
    int e = in_sizes[1] / 2;     // 800000

    static int smem_set = 0;
    if (!smem_set) {
        cudaFuncSetAttribute(k_fat, cudaFuncAttributeMaxDynamicSharedMemorySize, 114688);
        smem_set = 1;
    }

    k_fat<<<NPRE + NWORK, 512, 114688>>>(X, W1, EI, n, e);
    k_aggmm<<<(n + 63) / 64, 256>>>(b1, W2, n);
    k_agg2<<<(n + 7) / 8, 256>>>(b2, out, n);
}

// round 12
// speedup vs baseline: 1.1994x; 1.1994x over previous
#include <cuda_runtime.h>
#include <cuda_fp16.h>
#include <cstdint>

#define NN 100000
#define NE 800000
#define FIN 256
#define HID 128
#define NCLS 32
#define NPRE 128

// ---------------- scratch ----------------
__device__ int   g_cnt[NN];
__device__ int   g_rowptr[NN];
__device__ int   g_cursor[NN];
__device__ int   g_part[NPRE];
__device__ float g_dinv[NN];
__device__ int   g_csr[NE];
__device__ int   g_is64;
__device__ int   g_ready = 0;
__device__ int   g_ready2 = 0;
__device__ unsigned g_bar_cnt = 0;
__device__ volatile unsigned g_bar_gen = 0;
__device__ __align__(16) __half g_y1h[(size_t)NN * HID];   // dinv * (X@W1), fp16
__device__ __align__(16) __half g_y2h[(size_t)NN * NCLS];  // dinv * (h@W2), fp16
__device__ __align__(16) __half g_W1h[HID * FIN];          // W1^T fp16 [n][k]

// ---------------- helpers ----------------
__device__ __forceinline__ int load_idx(const void* p, long long i, int is64) {
    if (is64) return (int)((const long long*)p)[i];
    return ((const int*)p)[i];
}
__device__ __forceinline__ uint32_t smem_u32(const void* p) {
    uint32_t a;
    asm("{ .reg .u64 t; cvta.to.shared.u64 t, %1; cvt.u32.u64 %0, t; }" : "=r"(a) : "l"(p));
    return a;
}
__device__ __forceinline__ void ldsm4(uint4& r, uint32_t addr) {
    asm volatile("ldmatrix.sync.aligned.m8n8.x4.shared.b16 {%0,%1,%2,%3}, [%4];"
                 : "=r"(r.x), "=r"(r.y), "=r"(r.z), "=r"(r.w) : "r"(addr));
}
__device__ __forceinline__ void mma16816(float c[4], const uint4& a, uint32_t b0, uint32_t b1) {
    asm volatile(
        "mma.sync.aligned.m16n8k16.row.col.f32.f16.f16.f32 "
        "{%0,%1,%2,%3}, {%4,%5,%6,%7}, {%8,%9}, {%0,%1,%2,%3};"
        : "+f"(c[0]), "+f"(c[1]), "+f"(c[2]), "+f"(c[3])
        : "r"(a.x), "r"(a.y), "r"(a.z), "r"(a.w), "r"(b0), "r"(b1));
}
__device__ __forceinline__ uint32_t packh2(float a, float b) {
    __half2 h = __floats2half2_rn(a, b);
    return *(uint32_t*)&h;
}
__device__ __forceinline__ void cpasync16(uint32_t dst, const void* src) {
    asm volatile("cp.async.cg.shared.global [%0], [%1], 16;" :: "r"(dst), "l"(src));
}
#define CP_COMMIT() asm volatile("cp.async.commit_group;" ::: "memory")
#define CP_WAIT0()  asm volatile("cp.async.wait_group 0;" ::: "memory")

__device__ __forceinline__ void pre_grid_bar() {
    __syncthreads();
    if (threadIdx.x == 0) {
        __threadfence();
        unsigned g = g_bar_gen;
        if (atomicAdd(&g_bar_cnt, 1u) == NPRE - 1) {
            g_bar_cnt = 0;
            __threadfence();
            g_bar_gen = g + 1;
        } else {
            while (g_bar_gen == g) { __nanosleep(64); }
        }
    }
    __syncthreads();
}

__device__ __forceinline__ int block_exscan(int v, int* p_total, int* wsum) {
    const int lane = threadIdx.x & 31, w = threadIdx.x >> 5;
    const int nw = blockDim.x >> 5;
    int x = v;
#pragma unroll
    for (int o = 1; o < 32; o <<= 1) {
        int y = __shfl_up_sync(0xffffffffu, x, o);
        if (lane >= o) x += y;
    }
    if (lane == 31) wsum[w] = x;
    __syncthreads();
    if (w == 0) {
        int s = (lane < nw) ? wsum[lane] : 0;
#pragma unroll
        for (int o = 1; o < 32; o <<= 1) {
            int y = __shfl_up_sync(0xffffffffu, s, o);
            if (lane >= o) s += y;
        }
        wsum[lane] = s;
    }
    __syncthreads();
    int base = (w > 0) ? wsum[w - 1] : 0;
    *p_total = wsum[31];
    __syncthreads();
    return base + (x - v);
}

// ================= FAT: preproc (blocks < NPRE) + fp16-MMA GEMM1 via cp.async =================
// GEMM dyn smem (96 KB): [0,32K) A32 staging f32; [32K,64K) A16[2]; [64K,96K) B16[2]
__global__ __launch_bounds__(512, 2) void k_fat(const float* __restrict__ X,
                                                const float* __restrict__ W1,
                                                const void* __restrict__ ei,
                                                int n, int e) {
    extern __shared__ char dsm[];
    __shared__ int p_wsum[32];
    __shared__ int p_boff;
    const int tid = threadIdx.x;

    if (blockIdx.x < NPRE) {
        const int gt = blockIdx.x * 512 + tid;
        const int GT = NPRE * 512;
        for (int i = gt; i < n; i += GT) g_cnt[i] = 0;
        for (int i = gt; i < HID * FIN; i += GT) {
            int nn2 = i >> 8, k = i & 255;
            g_W1h[i] = __float2half(W1[(size_t)k * HID + nn2]);
        }
        if (gt == 0) {
            const long long* p = (const long long*)ei;
            int ok = 1;
            for (int j = 0; j < 256; j++) {
                long long v = p[j];
                if (v < 0 || v >= n) { ok = 0; break; }
            }
            g_is64 = ok;
        }
        pre_grid_bar();
        if (blockIdx.x == 0 && tid == 0) *(volatile int*)&g_ready = 1;
        const int is64 = g_is64;
        for (int i = gt; i < e; i += GT) {
            int d = load_idx(ei, (long long)e + i, is64);
            atomicAdd(&g_cnt[d], 1);
        }
        pre_grid_bar();
        const int L = (n + GT - 1) / GT;
        const int base = gt * L;
        const int end = (base + L < n) ? base + L : n;
        int s = 0;
        for (int i = base; i < end; i++) s += __ldcg(&g_cnt[i]);
        int tot;
        int ex = block_exscan(s, &tot, p_wsum);
        if (tid == 0) g_part[blockIdx.x] = tot;
        pre_grid_bar();
        {
            int v = (tid < NPRE) ? __ldcg(&g_part[tid]) : 0;
            int t2;
            int ex2 = block_exscan(v, &t2, p_wsum);
            if (tid == (int)blockIdx.x) p_boff = ex2;
            __syncthreads();
            int run = p_boff + ex;
            for (int i = base; i < end; i++) {
                int c = __ldcg(&g_cnt[i]);
                g_rowptr[i] = run;
                g_cursor[i] = run;
                g_dinv[i] = rsqrtf((float)(c + 1));
                run += c;
            }
        }
        pre_grid_bar();
        if (blockIdx.x == 0 && tid == 0) *(volatile int*)&g_ready2 = 1;
        for (int i = gt; i < e; i += GT) {
            int s0 = load_idx(ei, i, is64);
            int d0 = load_idx(ei, (long long)e + i, is64);
            int pos = atomicAdd(&g_cursor[d0], 1);
            g_csr[pos] = s0;
        }
        return;
    }

    // -------- GEMM1: 128x128 tile, BK=64, cp.async pipeline, warp grid 4x4 --------
    while (*(volatile int*)&g_ready == 0) { __nanosleep(128); }
    __threadfence();

    const int bid = blockIdx.x - NPRE;
    const int row0 = bid * 128;
    const int lane = tid & 31, warp = tid >> 5;
    const int wm = warp & 3, wn = warp >> 2;
    const uint32_t sbase = smem_u32(dsm);
    const uint32_t sA32 = sbase;
    const uint32_t sA16[2] = { sbase + 32768, sbase + 49152 };
    const uint32_t sB16[2] = { sbase + 65536, sbase + 81920 };

    float c[2][4][4];
#pragma unroll
    for (int i = 0; i < 2; i++)
#pragma unroll
        for (int j = 0; j < 4; j++)
#pragma unroll
            for (int v = 0; v < 4; v++) c[i][j][v] = 0.f;

    const int lrow = tid >> 2;
    const int lq = tid & 3;
    const int rsw = lrow & 7;
    int arow = row0 + lrow; if (arow >= n) arow = n - 1;
    const char* agp = (const char*)(X + (size_t)arow * FIN);
    const char* bgp = (const char*)(g_W1h + (size_t)lrow * FIN);

#define ISSUE_A32(kt) do {                                                    \
        _Pragma("unroll")                                                     \
        for (int j = 0; j < 4; j++)                                           \
            cpasync16(sA32 + lrow * 256 + lq * 64 + j * 16,                   \
                      agp + (kt) * 256 + lq * 64 + j * 16);                   \
    } while (0)
#define ISSUE_B(kt, bi) do {                                                  \
        _Pragma("unroll")                                                     \
        for (int j = 0; j < 2; j++) {                                         \
            int cc = lq * 2 + j;                                              \
            cpasync16(sB16[bi] + lrow * 128 + ((cc ^ rsw) * 16),              \
                      bgp + (kt) * 128 + cc * 16);                            \
        }                                                                     \
    } while (0)
#define CONVERT_A(bi) do {                                                    \
        _Pragma("unroll")                                                     \
        for (int j = 0; j < 2; j++) {                                         \
            int cc = lq * 2 + j;                                              \
            float4 v0, v1;                                                    \
            asm volatile("ld.shared.v4.f32 {%0,%1,%2,%3}, [%4];"              \
                : "=f"(v0.x), "=f"(v0.y), "=f"(v0.z), "=f"(v0.w)              \
                : "r"(sA32 + lrow * 256 + cc * 32));                          \
            asm volatile("ld.shared.v4.f32 {%0,%1,%2,%3}, [%4];"              \
                : "=f"(v1.x), "=f"(v1.y), "=f"(v1.z), "=f"(v1.w)              \
                : "r"(sA32 + lrow * 256 + cc * 32 + 16));                     \
            uint4 u = make_uint4(packh2(v0.x, v0.y), packh2(v0.z, v0.w),      \
                                 packh2(v1.x, v1.y), packh2(v1.z, v1.w));     \
            asm volatile("st.shared.v4.b32 [%0], {%1,%2,%3,%4};"              \
                :: "r"(sA16[bi] + lrow * 128 + ((cc ^ rsw) * 16)),            \
                   "r"(u.x), "r"(u.y), "r"(u.z), "r"(u.w));                   \
        }                                                                     \
    } while (0)

    ISSUE_A32(0); ISSUE_B(0, 0); CP_COMMIT();
    CP_WAIT0(); __syncthreads();
    CONVERT_A(0); __syncthreads();
    ISSUE_A32(1); ISSUE_B(1, 1); CP_COMMIT();

    const int lr = lane & 15, lhi = lane >> 4, lsw = lane & 7;
    for (int kt = 0; kt < FIN / 64; kt++) {
        const int bi = kt & 1;
#pragma unroll
        for (int kp = 0; kp < 4; kp++) {
            const int ch = ((kp * 2 + lhi) ^ lsw) * 16;
            uint4 af[2];
#pragma unroll
            for (int mt = 0; mt < 2; mt++)
                ldsm4(af[mt], sA16[bi] + (wm * 32 + mt * 16 + lr) * 128 + ch);
            uint4 bf[2];
#pragma unroll
            for (int bt = 0; bt < 2; bt++)
                ldsm4(bf[bt], sB16[bi] + (wn * 32 + bt * 16 + lr) * 128 + ch);
#pragma unroll
            for (int mt = 0; mt < 2; mt++)
#pragma unroll
                for (int bt = 0; bt < 2; bt++) {
                    mma16816(c[mt][2 * bt],     af[mt], bf[bt].x, bf[bt].z);
                    mma16816(c[mt][2 * bt + 1], af[mt], bf[bt].y, bf[bt].w);
                }
        }
        if (kt + 1 < FIN / 64) {
            CP_WAIT0(); __syncthreads();
            CONVERT_A((kt + 1) & 1);
            __syncthreads();
            if (kt + 2 < FIN / 64) { ISSUE_A32(kt + 2); ISSUE_B(kt + 2, (kt + 2) & 1); CP_COMMIT(); }
        }
    }

    // epilogue: y1 = dinv[r] * xw1[r], fp16
    while (*(volatile int*)&g_ready2 == 0) { __nanosleep(128); }
    __threadfence();
    const int g = lane >> 2, cp = (lane & 3) * 2;
#pragma unroll
    for (int mt = 0; mt < 2; mt++) {
        int r1 = row0 + wm * 32 + mt * 16 + g;
        int r2 = r1 + 8;
        float d1 = (r1 < n) ? g_dinv[r1] : 0.f;
        float d2 = (r2 < n) ? g_dinv[r2] : 0.f;
#pragma unroll
        for (int nt = 0; nt < 4; nt++) {
            int col = wn * 32 + nt * 8 + cp;
            if (r1 < n)
                *(__half2*)&g_y1h[(size_t)r1 * HID + col] =
                    __floats2half2_rn(d1 * c[mt][nt][0], d1 * c[mt][nt][1]);
            if (r2 < n)
                *(__half2*)&g_y1h[(size_t)r2 * HID + col] =
                    __floats2half2_rn(d2 * c[mt][nt][2], d2 * c[mt][nt][3]);
        }
    }
}

// ========== Agg1 + GEMM2 fused: y2 = dinv * (relu(dinv*(sum y1) + b1) @ W2), fp16 out ==========
__global__ __launch_bounds__(256) void k_aggmm(const float* __restrict__ b1,
                                               const float* __restrict__ W2, int n) {
    __shared__ __align__(16) __half hs[64 * 128];  // 16 KB
    __shared__ __align__(16) __half Bs[32 * 128];  // 8 KB
    const int tid = threadIdx.x, lane = tid & 31, warp = tid >> 5;
    const int row0 = blockIdx.x * 64;
    const uint32_t sH = smem_u32(hs), sB = smem_u32(Bs);

    {
        const int nn2 = tid >> 3;
        const int kc = (tid & 7) * 16;
        __half tmp[16];
#pragma unroll
        for (int k = 0; k < 16; k++) tmp[k] = __float2half(W2[(size_t)(kc + k) * NCLS + nn2]);
#pragma unroll
        for (int j = 0; j < 2; j++) {
            int cc = kc / 8 + j;
            *(uint4*)((char*)Bs + nn2 * 256 + ((cc ^ (nn2 & 7)) * 16)) = *(uint4*)&tmp[j * 8];
        }
    }

    float4 bb = ((const float4*)b1)[lane];
    const int hc = lane >> 1, hh = (lane & 1) * 8;
#pragma unroll 1
    for (int i = 0; i < 8; i++) {
        int node = row0 + warp * 8 + i;
        if (node >= n) break;
        int start = g_rowptr[node];
        int cnt = g_cnt[node];
        float di = g_dinv[node];
        uint2 sv = ((const uint2*)&g_y1h[(size_t)node * HID])[lane];
        float2 s0 = __half22float2(*(__half2*)&sv.x);
        float2 s1 = __half22float2(*(__half2*)&sv.y);
        float4 acc = make_float4(s0.x, s0.y, s1.x, s1.y);
        int t = 0;
        for (; t + 4 <= cnt; t += 4) {
            int e0 = g_csr[start + t],     e1 = g_csr[start + t + 1];
            int e2 = g_csr[start + t + 2], e3 = g_csr[start + t + 3];
            uint2 w0 = ((const uint2*)&g_y1h[(size_t)e0 * HID])[lane];
            uint2 w1 = ((const uint2*)&g_y1h[(size_t)e1 * HID])[lane];
            uint2 w2 = ((const uint2*)&g_y1h[(size_t)e2 * HID])[lane];
            uint2 w3 = ((const uint2*)&g_y1h[(size_t)e3 * HID])[lane];
            float2 a0 = __half22float2(*(__half2*)&w0.x), c0 = __half22float2(*(__half2*)&w0.y);
            float2 a1 = __half22float2(*(__half2*)&w1.x), c1 = __half22float2(*(__half2*)&w1.y);
            float2 a2 = __half22float2(*(__half2*)&w2.x), c2 = __half22float2(*(__half2*)&w2.y);
            float2 a3 = __half22float2(*(__half2*)&w3.x), c3 = __half22float2(*(__half2*)&w3.y);
            acc.x += (a0.x + a1.x) + (a2.x + a3.x);
            acc.y += (a0.y + a1.y) + (a2.y + a3.y);
            acc.z += (c0.x + c1.x) + (c2.x + c3.x);
            acc.w += (c0.y + c1.y) + (c2.y + c3.y);
        }
        for (; t < cnt; t++) {
            int e0 = g_csr[start + t];
            uint2 w0 = ((const uint2*)&g_y1h[(size_t)e0 * HID])[lane];
            float2 a0 = __half22float2(*(__half2*)&w0.x), c0 = __half22float2(*(__half2*)&w0.y);
            acc.x += a0.x; acc.y += a0.y; acc.z += c0.x; acc.w += c0.y;
        }
        float hx = fmaxf(fmaf(di, acc.x, bb.x), 0.f);
        float hy = fmaxf(fmaf(di, acc.y, bb.y), 0.f);
        float hz = fmaxf(fmaf(di, acc.z, bb.z), 0.f);
        float hw = fmaxf(fmaf(di, acc.w, bb.w), 0.f);
        int rl = warp * 8 + i;
        *(uint2*)((char*)hs + rl * 256 + ((hc ^ (rl & 7)) * 16) + hh) =
            make_uint2(packh2(hx, hy), packh2(hz, hw));
    }
    __syncthreads();

    const int wm = warp & 3, wn = warp >> 2;
    float c0[4] = {0.f, 0.f, 0.f, 0.f}, c1[4] = {0.f, 0.f, 0.f, 0.f};
    const int lr = lane & 15, lhi = lane >> 4, lsw = lane & 7;
#pragma unroll
    for (int kp = 0; kp < 8; kp++) {
        const int ch = ((kp * 2 + lhi) ^ lsw) * 16;
        uint4 af, bf;
        ldsm4(af, sH + (wm * 16 + lr) * 256 + ch);
        ldsm4(bf, sB + (wn * 16 + lr) * 256 + ch);
        mma16816(c0, af, bf.x, bf.z);
        mma16816(c1, af, bf.y, bf.w);
    }
    const int g = lane >> 2, cp = (lane & 3) * 2;
    int r1 = row0 + wm * 16 + g;
    int r2 = r1 + 8;
    float d1 = (r1 < n) ? g_dinv[r1] : 0.f;
    float d2 = (r2 < n) ? g_dinv[r2] : 0.f;
    int col = wn * 16 + cp;
    if (r1 < n) {
        *(__half2*)&g_y2h[(size_t)r1 * NCLS + col]     = __floats2half2_rn(d1 * c0[0], d1 * c0[1]);
        *(__half2*)&g_y2h[(size_t)r1 * NCLS + col + 8] = __floats2half2_rn(d1 * c1[0], d1 * c1[1]);
    }
    if (r2 < n) {
        *(__half2*)&g_y2h[(size_t)r2 * NCLS + col]     = __floats2half2_rn(d2 * c0[2], d2 * c0[3]);
        *(__half2*)&g_y2h[(size_t)r2 * NCLS + col + 8] = __floats2half2_rn(d2 * c1[2], d2 * c1[3]);
    }
}

// ---------------- Agg2 + log_softmax: fp16 gathers, 2-way unrolled ----------------
__global__ __launch_bounds__(256) void k_agg2(const float* __restrict__ b2,
                                              float* __restrict__ out, int n) {
    const int tid = threadIdx.x, lane = tid & 31;
    const int grp = lane >> 3, li = lane & 7;
    int node = blockIdx.x * 8 + (tid >> 5);
    if (node >= n) return;
    int start = g_rowptr[node];
    int cnt = g_cnt[node];
    float di = g_dinv[node];
    float4 acc = make_float4(0.f, 0.f, 0.f, 0.f);
    if (grp == 0) {
        uint2 w = ((const uint2*)&g_y2h[(size_t)node * NCLS])[li];
        float2 lo = __half22float2(*(__half2*)&w.x);
        float2 hi = __half22float2(*(__half2*)&w.y);
        acc = make_float4(lo.x, lo.y, hi.x, hi.y);
    }
    int t = grp;
    for (; t + 4 < cnt; t += 8) {
        int s0 = g_csr[start + t];
        int s1 = g_csr[start + t + 4];
        uint2 w0 = ((const uint2*)&g_y2h[(size_t)s0 * NCLS])[li];
        uint2 w1 = ((const uint2*)&g_y2h[(size_t)s1 * NCLS])[li];
        float2 lo0 = __half22float2(*(__half2*)&w0.x), hi0 = __half22float2(*(__half2*)&w0.y);
        float2 lo1 = __half22float2(*(__half2*)&w1.x), hi1 = __half22float2(*(__half2*)&w1.y);
        acc.x += lo0.x + lo1.x;
        acc.y += lo0.y + lo1.y;
        acc.z += hi0.x + hi1.x;
        acc.w += hi0.y + hi1.y;
    }
    if (t < cnt) {
        int s0 = g_csr[start + t];
        uint2 w = ((const uint2*)&g_y2h[(size_t)s0 * NCLS])[li];
        float2 lo = __half22float2(*(__half2*)&w.x);
        float2 hi = __half22float2(*(__half2*)&w.y);
        acc.x += lo.x; acc.y += lo.y; acc.z += hi.x; acc.w += hi.y;
    }
#pragma unroll
    for (int o = 8; o <= 16; o <<= 1) {
        acc.x += __shfl_xor_sync(0xffffffffu, acc.x, o);
        acc.y += __shfl_xor_sync(0xffffffffu, acc.y, o);
        acc.z += __shfl_xor_sync(0xffffffffu, acc.z, o);
        acc.w += __shfl_xor_sync(0xffffffffu, acc.w, o);
    }
    float4 bb = ((const float4*)b2)[li];
    float4 vv = make_float4(fmaf(di, acc.x, bb.x), fmaf(di, acc.y, bb.y),
                            fmaf(di, acc.z, bb.z), fmaf(di, acc.w, bb.w));
    float m = fmaxf(fmaxf(vv.x, vv.y), fmaxf(vv.z, vv.w));
#pragma unroll
    for (int o = 1; o <= 4; o <<= 1) m = fmaxf(m, __shfl_xor_sync(0xffffffffu, m, o));
    float s4 = __expf(vv.x - m) + __expf(vv.y - m) + __expf(vv.z - m) + __expf(vv.w - m);
#pragma unroll
    for (int o = 1; o <= 4; o <<= 1) s4 += __shfl_xor_sync(0xffffffffu, s4, o);
    float ls = m + logf(s4);
    if (lane < 8)
        ((float4*)&out[(size_t)node * NCLS])[li] =
            make_float4(vv.x - ls, vv.y - ls, vv.z - ls, vv.w - ls);
}

// ---------------- launch ----------------
extern "C" void kernel_launch(void* const* d_in, const int* in_sizes, int n_in,
                              void* d_out, int out_size) {
    const float* X = (const float*)d_in[0];
    const void* EI = d_in[1];
    const float* W1 = (const float*)d_in[2];
    const float* b1 = (const float*)d_in[3];
    const float* W2 = (const float*)d_in[4];
    const float* b2 = (const float*)d_in[5];
    float* out = (float*)d_out;

    int n = in_sizes[0] / FIN;   // 100000
    int e = in_sizes[1] / 2;     // 800000

    static int smem_set = 0;
    if (!smem_set) {
        cudaFuncSetAttribute(k_fat, cudaFuncAttributeMaxDynamicSharedMemorySize, 98304);
        smem_set = 1;
    }

    int g1blocks = (n + 127) / 128;  // 782
    k_fat<<<NPRE + g1blocks, 512, 98304>>>(X, W1, EI, n, e);
    k_aggmm<<<(n + 63) / 64, 256>>>(b1, W2, n);
    k_agg2<<<(n + 7) / 8, 256>>>(b2, out, n);
}